// round 1
// baseline (speedup 1.0000x reference)
#include <cuda_runtime.h>
#include <math_constants.h>

#define NEMB 8192
#define DIM 4
#define NTOK 32768           // 8 * 4096
#define NBLK 148
#define NTHR 256
#define SMEM_BYTES (NEMB * DIM * 4)   // 131072 bytes

__global__ void vq_init_kernel(float* out) { out[0] = 0.0f; }

__global__ __launch_bounds__(NTHR, 1)
void vq_main_kernel(const float* __restrict__ x,
                    const float* __restrict__ emb,
                    float* __restrict__ out) {
    extern __shared__ float4 se[];   // 8192 embeddings as float4

    // Cooperative load of the full table into shared memory (coalesced).
    const float4* e4 = (const float4*)emb;
    for (int i = threadIdx.x; i < NEMB; i += NTHR) se[i] = e4[i];
    __syncthreads();

    // Balanced token mapping: every SM (CTA) gets ~221 active threads.
    int token = threadIdx.x * NBLK + blockIdx.x;

    float lsum = 0.0f;
    if (token < NTOK) {
        const float4 xv = ((const float4*)x)[token];
        float best = -CUDART_INF_F;
        int bidx = 0;
        #pragma unroll 8
        for (int n = 0; n < NEMB; n++) {
            float4 e = se[n];
            float d = fmaf(xv.x, e.x,
                      fmaf(xv.y, e.y,
                      fmaf(xv.z, e.z, xv.w * e.w)));
            // strict '>' keeps the FIRST max index -> matches jnp.argmax
            if (d > best) { best = d; bidx = n; }
        }
        float4 e = se[bidx];
        lsum = fabsf(xv.x - e.x) + fabsf(xv.y - e.y)
             + fabsf(xv.z - e.z) + fabsf(xv.w - e.w);
    }

    // Warp reduce
    #pragma unroll
    for (int o = 16; o; o >>= 1)
        lsum += __shfl_down_sync(0xFFFFFFFFu, lsum, o);

    __shared__ float wsum[NTHR / 32];
    if ((threadIdx.x & 31) == 0) wsum[threadIdx.x >> 5] = lsum;
    __syncthreads();

    if (threadIdx.x == 0) {
        float s = 0.0f;
        #pragma unroll
        for (int i = 0; i < NTHR / 32; i++) s += wsum[i];
        // loss = reg + embedding = 2 * mean|x - e|; fold scale here so no
        // finalize kernel is needed.
        atomicAdd(out, s * (2.0f / (float)(NTOK * DIM)));
    }
}

extern "C" void kernel_launch(void* const* d_in, const int* in_sizes, int n_in,
                              void* d_out, int out_size) {
    const float* x   = (const float*)d_in[0];   // [8, 4096, 4] f32
    const float* emb = (const float*)d_in[1];   // [8192, 4] f32
    float* out = (float*)d_out;

    // 128KB dynamic smem needs an opt-in (idempotent; safe under capture).
    cudaFuncSetAttribute(vq_main_kernel,
                         cudaFuncAttributeMaxDynamicSharedMemorySize,
                         SMEM_BYTES);

    vq_init_kernel<<<1, 1>>>(out);
    vq_main_kernel<<<NBLK, NTHR, SMEM_BYTES>>>(x, emb, out);
}